// round 1
// baseline (speedup 1.0000x reference)
#include <cuda_runtime.h>
#include <cuda_bf16.h>

#define FULLMASK 0xffffffffu

static const int B = 64;
static const int S = 512;
static const int T = 16;      // tags
static const int K = 300;     // embed dim
static const int ROWS = B * S;           // 32768
static const int ROWS_PER_BLK = 64;

// ============================================================
// Kernel 1: probs[row][j] = sum_k embed[text[row]][k] * W[k][j] + b[j]
// Tiled mini-GEMM: 64 rows per block, 256 threads, k-chunks of 100.
// W transposed into smem with stride 308 (conflict-free LDS.128 across j).
// ============================================================
__global__ __launch_bounds__(256, 4)
void probs_kernel(const int* __restrict__ text,
                  const float* __restrict__ embed,
                  const float* __restrict__ W,
                  const float* __restrict__ bvec,
                  float* __restrict__ out) {
    __shared__ __align__(16) float Wt[16 * 308];   // Wt[j][k], padded stride
    __shared__ __align__(16) float Et[64 * 104];   // Et[r][k'], padded stride
    __shared__ int tok_sh[64];

    const int tid  = threadIdx.x;
    const int row0 = blockIdx.x * ROWS_PER_BLK;

    // stage W transposed
    for (int i = tid; i < K * T; i += 256) {
        int k = i >> 4, j = i & 15;
        Wt[j * 308 + k] = W[i];
    }
    if (tid < 64) tok_sh[tid] = text[row0 + tid];
    __syncthreads();

    const int j    = tid & 15;
    const int rg   = tid >> 4;      // 0..15, each owns 4 rows
    const int wrp  = tid >> 5;      // 0..7
    const int lane = tid & 31;

    float acc0 = 0.f, acc1 = 0.f, acc2 = 0.f, acc3 = 0.f;
    float4* Et4 = (float4*)Et;

    #pragma unroll
    for (int kc = 0; kc < 3; ++kc) {
        const int k0 = kc * 100;
        // stage 64 rows x 100 floats (25 float4 per row), one warp per 8 rows
        #pragma unroll
        for (int rb = 0; rb < 8; ++rb) {
            int r = wrp * 8 + rb;
            const float4* src = (const float4*)(embed + (size_t)tok_sh[r] * K + k0);
            if (lane < 25) Et4[r * 26 + lane] = src[lane];
        }
        __syncthreads();

        const float4* Wrow = (const float4*)(Wt + j * 308 + k0);
        const float* e0 = Et + (rg * 4 + 0) * 104;
        const float* e1 = Et + (rg * 4 + 1) * 104;
        const float* e2 = Et + (rg * 4 + 2) * 104;
        const float* e3 = Et + (rg * 4 + 3) * 104;

        #pragma unroll
        for (int k4 = 0; k4 < 25; ++k4) {
            float4 w  = Wrow[k4];
            float4 ea = *(const float4*)(e0 + k4 * 4);
            float4 eb = *(const float4*)(e1 + k4 * 4);
            float4 ec = *(const float4*)(e2 + k4 * 4);
            float4 ed = *(const float4*)(e3 + k4 * 4);
            acc0 = fmaf(ea.x, w.x, acc0); acc0 = fmaf(ea.y, w.y, acc0);
            acc0 = fmaf(ea.z, w.z, acc0); acc0 = fmaf(ea.w, w.w, acc0);
            acc1 = fmaf(eb.x, w.x, acc1); acc1 = fmaf(eb.y, w.y, acc1);
            acc1 = fmaf(eb.z, w.z, acc1); acc1 = fmaf(eb.w, w.w, acc1);
            acc2 = fmaf(ec.x, w.x, acc2); acc2 = fmaf(ec.y, w.y, acc2);
            acc2 = fmaf(ec.z, w.z, acc2); acc2 = fmaf(ec.w, w.w, acc2);
            acc3 = fmaf(ed.x, w.x, acc3); acc3 = fmaf(ed.y, w.y, acc3);
            acc3 = fmaf(ed.z, w.z, acc3); acc3 = fmaf(ed.w, w.w, acc3);
        }
        __syncthreads();
    }

    float bj = bvec[j];
    size_t base = (size_t)(row0 + rg * 4) * T + j;
    out[base]      = acc0 + bj;
    out[base + 16] = acc1 + bj;
    out[base + 32] = acc2 + bj;
    out[base + 48] = acc3 + bj;
}

// ============================================================
// Kernel 2: lens, unary, binary, CRF forward scan + log-likelihood.
// One warp per batch. Lanes 0..15 own tag j (lanes 16..31 mirror).
// Scan trick: lse_i(a_i + trans_ij) = log(sum_i e^{a_i} * E_ij),
// E precomputed; rebase (subtract max) every 8 steps; emit prefetch depth 8.
// ============================================================
__global__ __launch_bounds__(32, 1)
void crf_kernel(const int* __restrict__ text,
                const int* __restrict__ tags,
                const float* __restrict__ trans,
                const float* __restrict__ probs,
                float* __restrict__ out_tail) {
    const int b    = blockIdx.x;
    const int lane = threadIdx.x;

    __shared__ float tsh[256];
    for (int i = lane; i < 256; i += 32) tsh[i] = trans[i];
    __syncwarp();

    const int*   txt = text + b * S;
    const int*   tg  = tags + b * S;
    const float* P   = probs + (size_t)b * S * T;

    // ---- text_lens ----
    int cnt = 0;
    for (int s = lane; s < S; s += 32) cnt += (txt[s] != 0) ? 1 : 0;
    #pragma unroll
    for (int off = 16; off; off >>= 1) cnt += __shfl_xor_sync(FULLMASK, cnt, off);
    const int len = cnt;   // uniform

    // ---- unary + binary scores ----
    float u = 0.f, bsc = 0.f;
    for (int s = lane; s < S; s += 32) {
        if (s < len) {
            int t = tg[s];
            u += P[s * T + t];
            if (s >= 1) bsc += tsh[tg[s - 1] * T + t];
        }
    }
    #pragma unroll
    for (int off = 16; off; off >>= 1) {
        u   += __shfl_xor_sync(FULLMASK, u, off);
        bsc += __shfl_xor_sync(FULLMASK, bsc, off);
    }

    // ---- forward scan ----
    const int j = lane & 15;
    float E[16];
    #pragma unroll
    for (int i = 0; i < 16; ++i) E[i] = __expf(tsh[i * T + j]);

    float a     = P[j];     // alpha0
    float carry = 0.f;

    float eb[8];
    #pragma unroll
    for (int q = 0; q < 8; ++q) eb[q] = P[(1 + q) * T + j];

    for (int sb = 1; sb < S; sb += 8) {
        #pragma unroll
        for (int q = 0; q < 8; ++q) {
            int s  = sb + q;
            int sp = s + 8;
            float epref = 0.f;
            if (sp < S) epref = __ldg(P + sp * T + j);
            if (s < len) {           // uniform branch
                float p  = __expf(a);
                float t0 = __shfl_sync(FULLMASK, p, 0)  * E[0];
                float t1 = __shfl_sync(FULLMASK, p, 1)  * E[1];
                float t2 = __shfl_sync(FULLMASK, p, 2)  * E[2];
                float t3 = __shfl_sync(FULLMASK, p, 3)  * E[3];
                t0 = fmaf(__shfl_sync(FULLMASK, p, 4),  E[4],  t0);
                t1 = fmaf(__shfl_sync(FULLMASK, p, 5),  E[5],  t1);
                t2 = fmaf(__shfl_sync(FULLMASK, p, 6),  E[6],  t2);
                t3 = fmaf(__shfl_sync(FULLMASK, p, 7),  E[7],  t3);
                t0 = fmaf(__shfl_sync(FULLMASK, p, 8),  E[8],  t0);
                t1 = fmaf(__shfl_sync(FULLMASK, p, 9),  E[9],  t1);
                t2 = fmaf(__shfl_sync(FULLMASK, p, 10), E[10], t2);
                t3 = fmaf(__shfl_sync(FULLMASK, p, 11), E[11], t3);
                t0 = fmaf(__shfl_sync(FULLMASK, p, 12), E[12], t0);
                t1 = fmaf(__shfl_sync(FULLMASK, p, 13), E[13], t1);
                t2 = fmaf(__shfl_sync(FULLMASK, p, 14), E[14], t2);
                t3 = fmaf(__shfl_sync(FULLMASK, p, 15), E[15], t3);
                a = __logf((t0 + t1) + (t2 + t3)) + eb[q];
            }
            eb[q] = epref;
        }
        // rebase every 8 steps (growth bound ~4/step -> safe)
        float m = a;
        m = fmaxf(m, __shfl_xor_sync(FULLMASK, m, 8));
        m = fmaxf(m, __shfl_xor_sync(FULLMASK, m, 4));
        m = fmaxf(m, __shfl_xor_sync(FULLMASK, m, 2));
        m = fmaxf(m, __shfl_xor_sync(FULLMASK, m, 1));
        a -= m;
        carry += m;
    }

    // ---- log_norm = carry + logsumexp(a) ----
    float m = a;
    m = fmaxf(m, __shfl_xor_sync(FULLMASK, m, 8));
    m = fmaxf(m, __shfl_xor_sync(FULLMASK, m, 4));
    m = fmaxf(m, __shfl_xor_sync(FULLMASK, m, 2));
    m = fmaxf(m, __shfl_xor_sync(FULLMASK, m, 1));
    float ex = __expf(a - m);
    ex += __shfl_xor_sync(FULLMASK, ex, 8);
    ex += __shfl_xor_sync(FULLMASK, ex, 4);
    ex += __shfl_xor_sync(FULLMASK, ex, 2);
    ex += __shfl_xor_sync(FULLMASK, ex, 1);
    float logn = carry + m + __logf(ex);

    if (lane == 0) {
        out_tail[b]      = (float)len;        // text_lens
        out_tail[B + b]  = u + bsc - logn;    // log_likelihood
    }
}

// ============================================================
// kernel_launch
// inputs: text(i32 64x512), tags(i32 64x512), embed(f32 50000x300),
//         W(f32 300x16), b(f32 16), trans(f32 16x16)
// output (f32): [probs 64*512*16 | text_lens 64 | log_likelihood 64]
// ============================================================
extern "C" void kernel_launch(void* const* d_in, const int* in_sizes, int n_in,
                              void* d_out, int out_size) {
    const int*   text  = (const int*)d_in[0];
    const int*   tags  = (const int*)d_in[1];
    const float* embed = (const float*)d_in[2];
    const float* W     = (const float*)d_in[3];
    const float* bvec  = (const float*)d_in[4];
    const float* trans = (const float*)d_in[5];
    float* out = (float*)d_out;

    probs_kernel<<<ROWS / ROWS_PER_BLK, 256>>>(text, embed, W, bvec, out);
    crf_kernel<<<B, 32>>>(text, tags, trans, out, out + (size_t)ROWS * T);
}

// round 2
// speedup vs baseline: 1.5557x; 1.5557x over previous
#include <cuda_runtime.h>
#include <cuda_bf16.h>

#define FULLMASK 0xffffffffu

static const int B = 64;
static const int S = 512;
static const int T = 16;      // tags
static const int K = 300;     // embed dim
static const int ROWS = B * S;           // 32768
static const int ROWS_PER_BLK = 64;
static const int C = 8;       // chunks per sequence
static const int L = 64;      // steps per chunk (covers s=1..512, last partial)

// scratch (no allocations allowed -> device globals)
__device__ float g_Mexp[B * C * T * T];   // exp(M - rowmax), row-normalized
__device__ float g_carry[B * C * T];      // per-row log carry (incl rowmax)

// ============================================================
// Kernel 1: probs[row][j] = sum_k embed[text[row]][k] * W[k][j] + b[j]
// ============================================================
__global__ __launch_bounds__(256, 4)
void probs_kernel(const int* __restrict__ text,
                  const float* __restrict__ embed,
                  const float* __restrict__ W,
                  const float* __restrict__ bvec,
                  float* __restrict__ out) {
    __shared__ __align__(16) float Wt[16 * 308];
    __shared__ __align__(16) float Et[64 * 104];
    __shared__ int tok_sh[64];

    const int tid  = threadIdx.x;
    const int row0 = blockIdx.x * ROWS_PER_BLK;

    for (int i = tid; i < K * T; i += 256) {
        int k = i >> 4, j = i & 15;
        Wt[j * 308 + k] = W[i];
    }
    if (tid < 64) tok_sh[tid] = text[row0 + tid];
    __syncthreads();

    const int j    = tid & 15;
    const int rg   = tid >> 4;
    const int wrp  = tid >> 5;
    const int lane = tid & 31;

    float acc0 = 0.f, acc1 = 0.f, acc2 = 0.f, acc3 = 0.f;
    float4* Et4 = (float4*)Et;

    #pragma unroll
    for (int kc = 0; kc < 3; ++kc) {
        const int k0 = kc * 100;
        #pragma unroll
        for (int rb = 0; rb < 8; ++rb) {
            int r = wrp * 8 + rb;
            const float4* src = (const float4*)(embed + (size_t)tok_sh[r] * K + k0);
            if (lane < 25) Et4[r * 26 + lane] = src[lane];
        }
        __syncthreads();

        const float4* Wrow = (const float4*)(Wt + j * 308 + k0);
        const float* e0 = Et + (rg * 4 + 0) * 104;
        const float* e1 = Et + (rg * 4 + 1) * 104;
        const float* e2 = Et + (rg * 4 + 2) * 104;
        const float* e3 = Et + (rg * 4 + 3) * 104;

        #pragma unroll
        for (int k4 = 0; k4 < 25; ++k4) {
            float4 w  = Wrow[k4];
            float4 ea = *(const float4*)(e0 + k4 * 4);
            float4 eb = *(const float4*)(e1 + k4 * 4);
            float4 ec = *(const float4*)(e2 + k4 * 4);
            float4 ed = *(const float4*)(e3 + k4 * 4);
            acc0 = fmaf(ea.x, w.x, acc0); acc0 = fmaf(ea.y, w.y, acc0);
            acc0 = fmaf(ea.z, w.z, acc0); acc0 = fmaf(ea.w, w.w, acc0);
            acc1 = fmaf(eb.x, w.x, acc1); acc1 = fmaf(eb.y, w.y, acc1);
            acc1 = fmaf(eb.z, w.z, acc1); acc1 = fmaf(eb.w, w.w, acc1);
            acc2 = fmaf(ec.x, w.x, acc2); acc2 = fmaf(ec.y, w.y, acc2);
            acc2 = fmaf(ec.z, w.z, acc2); acc2 = fmaf(ec.w, w.w, acc2);
            acc3 = fmaf(ed.x, w.x, acc3); acc3 = fmaf(ed.y, w.y, acc3);
            acc3 = fmaf(ed.z, w.z, acc3); acc3 = fmaf(ed.w, w.w, acc3);
        }
        __syncthreads();
    }

    float bj = bvec[j];
    size_t base = (size_t)(row0 + rg * 4) * T + j;
    out[base]      = acc0 + bj;
    out[base + 16] = acc1 + bj;
    out[base + 32] = acc2 + bj;
    out[base + 48] = acc3 + bj;
}

// ============================================================
// Kernel 2: per-(batch, chunk) transfer matrix in LINEAR domain.
// 256 threads = 16 rows x 16 lanes; row i starts one-hot e_i.
// step: p_j' = (sum_k p_k * E[k][j]) * exp(emit[s][j]),  masked if s >= len.
// Renormalize by row max every 8 steps, carry accumulates log(max).
// Stores row-normalized exp-matrix + carry.
// ============================================================
__global__ __launch_bounds__(256, 4)
void chunk_kernel(const int* __restrict__ text,
                  const float* __restrict__ trans,
                  const float* __restrict__ probs) {
    const int c   = blockIdx.x;
    const int b   = blockIdx.y;
    const int tid = threadIdx.x;
    const int j   = tid & 15;
    const int row = tid >> 4;

    __shared__ float tsh[256];
    __shared__ float esh[L * 16];
    __shared__ int   lred[8];

    const float* P  = probs + (size_t)b * S * T;
    const int s0    = 1 + c * L;
    const int send  = min(s0 + L, S);
    const int nload = (send - s0) * 16;

    tsh[tid] = trans[tid];

    // sequence length (token != 0 count)
    const int* txt = text + b * S;
    int cnt = (txt[tid] != 0 ? 1 : 0) + (txt[tid + 256] != 0 ? 1 : 0);
    #pragma unroll
    for (int off = 16; off; off >>= 1) cnt += __shfl_xor_sync(FULLMASK, cnt, off);
    if ((tid & 31) == 0) lred[tid >> 5] = cnt;

    // stage exp(emit) for this chunk
    #pragma unroll
    for (int it = 0; it < 4; ++it) {
        int i = tid + it * 256;
        esh[i] = (i < nload) ? __expf(P[s0 * 16 + i]) : 1.0f;
    }
    __syncthreads();

    int len = 0;
    #pragma unroll
    for (int wgi = 0; wgi < 8; ++wgi) len += lred[wgi];
    const int lenc = min(len, S);

    float E[16];
    #pragma unroll
    for (int k = 0; k < 16; ++k) E[k] = __expf(tsh[k * 16 + j]);

    float p     = (row == j) ? 1.0f : 0.0f;
    float carry = 0.0f;

    for (int qb = 0; qb < L; qb += 8) {
        #pragma unroll
        for (int q2 = 0; q2 < 8; ++q2) {
            const int q = qb + q2;
            const int s = s0 + q;
            const float em = esh[q * 16 + j];
            float t0 = __shfl_sync(FULLMASK, p, 0, 16)  * E[0];
            float t1 = __shfl_sync(FULLMASK, p, 1, 16)  * E[1];
            float t2 = __shfl_sync(FULLMASK, p, 2, 16)  * E[2];
            float t3 = __shfl_sync(FULLMASK, p, 3, 16)  * E[3];
            t0 = fmaf(__shfl_sync(FULLMASK, p, 4, 16),  E[4],  t0);
            t1 = fmaf(__shfl_sync(FULLMASK, p, 5, 16),  E[5],  t1);
            t2 = fmaf(__shfl_sync(FULLMASK, p, 6, 16),  E[6],  t2);
            t3 = fmaf(__shfl_sync(FULLMASK, p, 7, 16),  E[7],  t3);
            t0 = fmaf(__shfl_sync(FULLMASK, p, 8, 16),  E[8],  t0);
            t1 = fmaf(__shfl_sync(FULLMASK, p, 9, 16),  E[9],  t1);
            t2 = fmaf(__shfl_sync(FULLMASK, p, 10, 16), E[10], t2);
            t3 = fmaf(__shfl_sync(FULLMASK, p, 11, 16), E[11], t3);
            t0 = fmaf(__shfl_sync(FULLMASK, p, 12, 16), E[12], t0);
            t1 = fmaf(__shfl_sync(FULLMASK, p, 13, 16), E[13], t1);
            t2 = fmaf(__shfl_sync(FULLMASK, p, 14, 16), E[14], t2);
            t3 = fmaf(__shfl_sync(FULLMASK, p, 15, 16), E[15], t3);
            float pn = ((t0 + t1) + (t2 + t3)) * em;
            p = (s < lenc) ? pn : p;
        }
        // renormalize row by its max; accumulate log in carry
        float mx = p;
        mx = fmaxf(mx, __shfl_xor_sync(FULLMASK, mx, 1, 16));
        mx = fmaxf(mx, __shfl_xor_sync(FULLMASK, mx, 2, 16));
        mx = fmaxf(mx, __shfl_xor_sync(FULLMASK, mx, 4, 16));
        mx = fmaxf(mx, __shfl_xor_sync(FULLMASK, mx, 8, 16));
        carry += __logf(mx);
        p *= (1.0f / mx);
    }

    g_Mexp[((b * C + c) * 16 + row) * 16 + j] = p;
    if (j == 0) g_carry[(b * C + c) * 16 + row] = carry;
}

// ============================================================
// Kernel 3: per-batch — len, unary, binary, fold alpha0 through the
// C chunk matrices, final logsumexp -> log-likelihood.
// ============================================================
__global__ __launch_bounds__(32, 1)
void combine_kernel(const int* __restrict__ text,
                    const int* __restrict__ tags,
                    const float* __restrict__ trans,
                    const float* __restrict__ probs,
                    float* __restrict__ out_tail) {
    const int b    = blockIdx.x;
    const int lane = threadIdx.x;
    const int j    = lane & 15;

    __shared__ float tsh[256];
    __shared__ float MshT[C * 16 * 16];   // [c][j][i] (transposed for float4 dot)
    __shared__ float csh[C * 16];
    __shared__ float psh[16];

    for (int i = lane; i < 256; i += 32) tsh[i] = trans[i];
    const float* Mb = g_Mexp + (size_t)b * C * 256;
    for (int i = lane; i < C * 256; i += 32) {
        int cc = i >> 8, r = (i >> 4) & 15, jj = i & 15;
        MshT[cc * 256 + jj * 16 + r] = Mb[i];
    }
    for (int i = lane; i < C * 16; i += 32) csh[i] = g_carry[b * C * 16 + i];
    __syncwarp();

    const int*   txt = text + b * S;
    const int*   tg  = tags + b * S;
    const float* P   = probs + (size_t)b * S * T;

    // text_lens
    int cnt = 0;
    for (int s = lane; s < S; s += 32) cnt += (txt[s] != 0) ? 1 : 0;
    #pragma unroll
    for (int off = 16; off; off >>= 1) cnt += __shfl_xor_sync(FULLMASK, cnt, off);
    const int len = cnt;

    // unary + binary
    float u = 0.f, bsc = 0.f;
    for (int s = lane; s < S; s += 32) {
        if (s < len) {
            int t = tg[s];
            u += P[s * T + t];
            if (s >= 1) bsc += tsh[tg[s - 1] * T + t];
        }
    }
    #pragma unroll
    for (int off = 16; off; off >>= 1) {
        u   += __shfl_xor_sync(FULLMASK, u, off);
        bsc += __shfl_xor_sync(FULLMASK, bsc, off);
    }

    // fold alpha0 through chunk matrices
    float v = P[j];
    #pragma unroll
    for (int cc = 0; cc < C; ++cc) {
        float w = v + csh[cc * 16 + j];
        float m = w;
        m = fmaxf(m, __shfl_xor_sync(FULLMASK, m, 1, 16));
        m = fmaxf(m, __shfl_xor_sync(FULLMASK, m, 2, 16));
        m = fmaxf(m, __shfl_xor_sync(FULLMASK, m, 4, 16));
        m = fmaxf(m, __shfl_xor_sync(FULLMASK, m, 8, 16));
        float pi = __expf(w - m);
        if (lane < 16) psh[lane] = pi;
        __syncwarp();
        const float4* col = (const float4*)(MshT + cc * 256 + j * 16);
        const float4* pp  = (const float4*)psh;
        float acc = 0.f;
        #pragma unroll
        for (int q = 0; q < 4; ++q) {
            float4 a  = col[q];
            float4 c4 = pp[q];
            acc = fmaf(a.x, c4.x, acc);
            acc = fmaf(a.y, c4.y, acc);
            acc = fmaf(a.z, c4.z, acc);
            acc = fmaf(a.w, c4.w, acc);
        }
        v = __logf(acc) + m;
        __syncwarp();
    }

    // log_norm = lse(v)
    float m = v;
    m = fmaxf(m, __shfl_xor_sync(FULLMASK, m, 1, 16));
    m = fmaxf(m, __shfl_xor_sync(FULLMASK, m, 2, 16));
    m = fmaxf(m, __shfl_xor_sync(FULLMASK, m, 4, 16));
    m = fmaxf(m, __shfl_xor_sync(FULLMASK, m, 8, 16));
    float ex = __expf(v - m);
    ex += __shfl_xor_sync(FULLMASK, ex, 1, 16);
    ex += __shfl_xor_sync(FULLMASK, ex, 2, 16);
    ex += __shfl_xor_sync(FULLMASK, ex, 4, 16);
    ex += __shfl_xor_sync(FULLMASK, ex, 8, 16);
    float logn = m + __logf(ex);

    if (lane == 0) {
        out_tail[b]     = (float)len;
        out_tail[B + b] = u + bsc - logn;
    }
}

// ============================================================
extern "C" void kernel_launch(void* const* d_in, const int* in_sizes, int n_in,
                              void* d_out, int out_size) {
    const int*   text  = (const int*)d_in[0];
    const int*   tags  = (const int*)d_in[1];
    const float* embed = (const float*)d_in[2];
    const float* W     = (const float*)d_in[3];
    const float* bvec  = (const float*)d_in[4];
    const float* trans = (const float*)d_in[5];
    float* out = (float*)d_out;

    probs_kernel<<<ROWS / ROWS_PER_BLK, 256>>>(text, embed, W, bvec, out);
    chunk_kernel<<<dim3(C, B), 256>>>(text, trans, out);
    combine_kernel<<<B, 32>>>(text, tags, trans, out, out + (size_t)ROWS * T);
}